// round 1
// baseline (speedup 1.0000x reference)
#include <cuda_runtime.h>
#include <math.h>

// Problem dims (fixed)
#define N_TOK  4096          // B*T
#define DIM    512           // D
#define N_EXP  16            // E
#define TOPK   4             // K
#define HID    2048          // H
#define N_PAIR (N_TOK*TOPK)  // 16384

// ---------------- scratch (device globals; no runtime alloc) ----------------
__device__ float g_h  [N_TOK * DIM];                 // projected tokens (per view)
__device__ float g_r  [N_TOK * DIM];                 // routed tokens
__device__ float g_hid [(size_t)N_PAIR * HID];       // expert hidden (128 MB)
__device__ float g_slot[(size_t)N_PAIR * DIM];       // gated expert output per pair
__device__ int   g_pair_token[N_PAIR];
__device__ float g_pair_gate [N_PAIR];
__device__ int   g_pairpos   [N_TOK * TOPK];         // (token,slot) -> pair position
__device__ int   g_tok_eidx  [N_TOK * TOPK];
__device__ float g_tok_gate  [N_TOK * TOPK];
__device__ int   g_counts [N_EXP];
__device__ int   g_offsets[N_EXP + 1];
__device__ int   g_cursor [N_EXP];

__device__ __forceinline__ float gelu_exact(float x) {
    return 0.5f * x * (1.0f + erff(x * 0.70710678118654752440f));
}

// ---------------- generic SGEMM: C[M,N] = A[M,K] @ B[K,N] (+bias) -----------
// BM=128, BN=64, BK=16, 256 threads, 8x4 per-thread microtile.
template<bool HAS_BIAS>
__global__ __launch_bounds__(256) void sgemm_kernel(
    const float* __restrict__ A, const float* __restrict__ B,
    const float* __restrict__ bias, float* __restrict__ C,
    int M, int N, int K)
{
    __shared__ float As[16][128];
    __shared__ float Bs[16][64];
    const int tid = threadIdx.x;
    const int ty = tid >> 4, tx = tid & 15;
    const int m0 = blockIdx.y * 128;
    const int n0 = blockIdx.x * 64;

    const int la_m = tid >> 1;            // 0..127
    const int la_k = (tid & 1) << 3;      // 0 or 8
    const int lb_k = tid >> 4;            // 0..15
    const int lb_n = (tid & 15) << 2;     // 0..60

    const bool a_valid = (m0 + la_m) < M;
    const float* Arow = A + (size_t)(m0 + la_m) * K + la_k;
    const float* Bptr = B + (size_t)lb_k * N + n0 + lb_n;

    float acc[8][4];
#pragma unroll
    for (int i = 0; i < 8; i++)
#pragma unroll
        for (int j = 0; j < 4; j++) acc[i][j] = 0.f;

    for (int k0 = 0; k0 < K; k0 += 16) {
        float4 a0 = make_float4(0.f,0.f,0.f,0.f), a1 = a0;
        if (a_valid) {
            a0 = *(const float4*)(Arow + k0);
            a1 = *(const float4*)(Arow + k0 + 4);
        }
        float4 b = *(const float4*)(Bptr + (size_t)k0 * N);
        __syncthreads();
        As[la_k+0][la_m] = a0.x; As[la_k+1][la_m] = a0.y;
        As[la_k+2][la_m] = a0.z; As[la_k+3][la_m] = a0.w;
        As[la_k+4][la_m] = a1.x; As[la_k+5][la_m] = a1.y;
        As[la_k+6][la_m] = a1.z; As[la_k+7][la_m] = a1.w;
        *(float4*)&Bs[lb_k][lb_n] = b;
        __syncthreads();
#pragma unroll
        for (int kk = 0; kk < 16; kk++) {
            float4 av0 = *(const float4*)&As[kk][ty*8];
            float4 av1 = *(const float4*)&As[kk][ty*8+4];
            float4 bv  = *(const float4*)&Bs[kk][tx*4];
            float a[8] = {av0.x,av0.y,av0.z,av0.w,av1.x,av1.y,av1.z,av1.w};
            float bb[4] = {bv.x,bv.y,bv.z,bv.w};
#pragma unroll
            for (int i = 0; i < 8; i++)
#pragma unroll
                for (int j = 0; j < 4; j++)
                    acc[i][j] = fmaf(a[i], bb[j], acc[i][j]);
        }
    }

    float bvals[4] = {0.f,0.f,0.f,0.f};
    if (HAS_BIAS) {
#pragma unroll
        for (int j = 0; j < 4; j++) bvals[j] = bias[n0 + tx*4 + j];
    }
#pragma unroll
    for (int i = 0; i < 8; i++) {
        int row = m0 + ty*8 + i;
        if (row < M) {
            float4 v = make_float4(acc[i][0]+bvals[0], acc[i][1]+bvals[1],
                                   acc[i][2]+bvals[2], acc[i][3]+bvals[3]);
            *(float4*)(C + (size_t)row * N + n0 + tx*4) = v;
        }
    }
}

// ---------------- gate: -cdist to expert keys, top-4 softmax ----------------
__global__ __launch_bounds__(128) void gate_kernel(const float* __restrict__ keys)
{
    const int t = blockIdx.x;
    __shared__ float rs[DIM];
    __shared__ float part[N_EXP][8];
    __shared__ float logit[N_EXP];
    const int tid = threadIdx.x;

    for (int i = tid; i < DIM; i += 128) rs[i] = g_r[(size_t)t * DIM + i];
    __syncthreads();

    const int e = tid >> 3;   // 0..15
    const int l = tid & 7;    // 0..7
    const float* kp = keys + (size_t)e * DIM;
    float s = 0.f;
    for (int i = l; i < DIM; i += 8) {
        float d = rs[i] - kp[i];
        s = fmaf(d, d, s);
    }
    part[e][l] = s;
    __syncthreads();
    if (l == 0) {
        float d2 = 0.f;
#pragma unroll
        for (int j = 0; j < 8; j++) d2 += part[e][j];
        logit[e] = -sqrtf(fmaxf(d2, 0.f));
    }
    __syncthreads();
    if (tid == 0) {
        float lv[N_EXP];
#pragma unroll
        for (int i = 0; i < N_EXP; i++) lv[i] = logit[i];
        int   idx[TOPK];
        float val[TOPK];
        bool used[N_EXP];
#pragma unroll
        for (int i = 0; i < N_EXP; i++) used[i] = false;
        for (int s2 = 0; s2 < TOPK; s2++) {
            int bi = -1; float bv = -1e30f;
            for (int i = 0; i < N_EXP; i++)
                if (!used[i] && lv[i] > bv) { bv = lv[i]; bi = i; }
            used[bi] = true; idx[s2] = bi; val[s2] = bv;
        }
        float mx = val[0];   // descending order, val[0] is max
        float ex[TOPK], se = 0.f;
        for (int s2 = 0; s2 < TOPK; s2++) { ex[s2] = expf(val[s2] - mx); se += ex[s2]; }
        float inv = 1.0f / se;
        for (int s2 = 0; s2 < TOPK; s2++) {
            g_tok_eidx[t*TOPK + s2] = idx[s2];
            g_tok_gate[t*TOPK + s2] = ex[s2] * inv;
            atomicAdd(&g_counts[idx[s2]], 1);
        }
    }
}

__global__ void zero_counts_kernel() {
    if (threadIdx.x < N_EXP) g_counts[threadIdx.x] = 0;
}

__global__ void scan_kernel() {
    if (threadIdx.x == 0) {
        int o = 0;
        for (int e = 0; e < N_EXP; e++) {
            g_offsets[e] = o;
            g_cursor[e]  = o;
            o += g_counts[e];
        }
        g_offsets[N_EXP] = o;
    }
}

__global__ __launch_bounds__(128) void scatter_kernel() {
    int t = blockIdx.x * 128 + threadIdx.x;
    if (t >= N_TOK) return;
    for (int s = 0; s < TOPK; s++) {
        int e = g_tok_eidx[t*TOPK + s];
        int p = atomicAdd(&g_cursor[e], 1);
        g_pair_token[p] = t;
        g_pair_gate[p]  = g_tok_gate[t*TOPK + s];
        g_pairpos[t*TOPK + s] = p;
    }
}

// ---------------- FFN1: hid[p,:] = gelu(h[tok(p)] @ w1[e] + b1[e]) ----------
__global__ __launch_bounds__(256) void ffn1_kernel(
    const float* __restrict__ w1, const float* __restrict__ b1)
{
    const int e   = blockIdx.z;
    const int off = g_offsets[e];
    const int cnt = g_offsets[e+1] - off;
    const int m0  = blockIdx.y * 128;
    if (m0 >= cnt) return;
    const int n0  = blockIdx.x * 64;

    __shared__ float As[16][128];
    __shared__ float Bs[16][64];
    const int tid = threadIdx.x;
    const int ty = tid >> 4, tx = tid & 15;
    const int la_m = tid >> 1;
    const int la_k = (tid & 1) << 3;
    const int lb_k = tid >> 4;
    const int lb_n = (tid & 15) << 2;

    const bool a_valid = (m0 + la_m) < cnt;
    const int token = a_valid ? g_pair_token[off + m0 + la_m] : 0;
    const float* Arow = g_h + (size_t)token * DIM + la_k;
    const float* Bptr = w1 + (size_t)e * DIM * HID + (size_t)lb_k * HID + n0 + lb_n;

    float acc[8][4];
#pragma unroll
    for (int i = 0; i < 8; i++)
#pragma unroll
        for (int j = 0; j < 4; j++) acc[i][j] = 0.f;

    for (int k0 = 0; k0 < DIM; k0 += 16) {
        float4 a0 = make_float4(0.f,0.f,0.f,0.f), a1 = a0;
        if (a_valid) {
            a0 = *(const float4*)(Arow + k0);
            a1 = *(const float4*)(Arow + k0 + 4);
        }
        float4 b = *(const float4*)(Bptr + (size_t)k0 * HID);
        __syncthreads();
        As[la_k+0][la_m] = a0.x; As[la_k+1][la_m] = a0.y;
        As[la_k+2][la_m] = a0.z; As[la_k+3][la_m] = a0.w;
        As[la_k+4][la_m] = a1.x; As[la_k+5][la_m] = a1.y;
        As[la_k+6][la_m] = a1.z; As[la_k+7][la_m] = a1.w;
        *(float4*)&Bs[lb_k][lb_n] = b;
        __syncthreads();
#pragma unroll
        for (int kk = 0; kk < 16; kk++) {
            float4 av0 = *(const float4*)&As[kk][ty*8];
            float4 av1 = *(const float4*)&As[kk][ty*8+4];
            float4 bv  = *(const float4*)&Bs[kk][tx*4];
            float a[8] = {av0.x,av0.y,av0.z,av0.w,av1.x,av1.y,av1.z,av1.w};
            float bb[4] = {bv.x,bv.y,bv.z,bv.w};
#pragma unroll
            for (int i = 0; i < 8; i++)
#pragma unroll
                for (int j = 0; j < 4; j++)
                    acc[i][j] = fmaf(a[i], bb[j], acc[i][j]);
        }
    }

    float bvals[4];
#pragma unroll
    for (int j = 0; j < 4; j++) bvals[j] = b1[(size_t)e * HID + n0 + tx*4 + j];
#pragma unroll
    for (int i = 0; i < 8; i++) {
        int row = m0 + ty*8 + i;
        if (row < cnt) {
            int p = off + row;
            float4 v;
            v.x = gelu_exact(acc[i][0] + bvals[0]);
            v.y = gelu_exact(acc[i][1] + bvals[1]);
            v.z = gelu_exact(acc[i][2] + bvals[2]);
            v.w = gelu_exact(acc[i][3] + bvals[3]);
            *(float4*)(g_hid + (size_t)p * HID + n0 + tx*4) = v;
        }
    }
}

// ---------------- FFN2: slot[p,:] = gate[p] * (hid[p] @ w2[e] + b2[e]) ------
__global__ __launch_bounds__(256) void ffn2_kernel(
    const float* __restrict__ w2, const float* __restrict__ b2)
{
    const int e   = blockIdx.z;
    const int off = g_offsets[e];
    const int cnt = g_offsets[e+1] - off;
    const int m0  = blockIdx.y * 128;
    if (m0 >= cnt) return;
    const int n0  = blockIdx.x * 64;

    __shared__ float As[16][128];
    __shared__ float Bs[16][64];
    const int tid = threadIdx.x;
    const int ty = tid >> 4, tx = tid & 15;
    const int la_m = tid >> 1;
    const int la_k = (tid & 1) << 3;
    const int lb_k = tid >> 4;
    const int lb_n = (tid & 15) << 2;

    const bool a_valid = (m0 + la_m) < cnt;
    const float* Arow = g_hid + (size_t)(off + (a_valid ? (m0 + la_m) : 0)) * HID + la_k;
    const float* Bptr = w2 + (size_t)e * HID * DIM + (size_t)lb_k * DIM + n0 + lb_n;

    float acc[8][4];
#pragma unroll
    for (int i = 0; i < 8; i++)
#pragma unroll
        for (int j = 0; j < 4; j++) acc[i][j] = 0.f;

    for (int k0 = 0; k0 < HID; k0 += 16) {
        float4 a0 = make_float4(0.f,0.f,0.f,0.f), a1 = a0;
        if (a_valid) {
            a0 = *(const float4*)(Arow + k0);
            a1 = *(const float4*)(Arow + k0 + 4);
        }
        float4 b = *(const float4*)(Bptr + (size_t)k0 * DIM);
        __syncthreads();
        As[la_k+0][la_m] = a0.x; As[la_k+1][la_m] = a0.y;
        As[la_k+2][la_m] = a0.z; As[la_k+3][la_m] = a0.w;
        As[la_k+4][la_m] = a1.x; As[la_k+5][la_m] = a1.y;
        As[la_k+6][la_m] = a1.z; As[la_k+7][la_m] = a1.w;
        *(float4*)&Bs[lb_k][lb_n] = b;
        __syncthreads();
#pragma unroll
        for (int kk = 0; kk < 16; kk++) {
            float4 av0 = *(const float4*)&As[kk][ty*8];
            float4 av1 = *(const float4*)&As[kk][ty*8+4];
            float4 bv  = *(const float4*)&Bs[kk][tx*4];
            float a[8] = {av0.x,av0.y,av0.z,av0.w,av1.x,av1.y,av1.z,av1.w};
            float bb[4] = {bv.x,bv.y,bv.z,bv.w};
#pragma unroll
            for (int i = 0; i < 8; i++)
#pragma unroll
                for (int j = 0; j < 4; j++)
                    acc[i][j] = fmaf(a[i], bb[j], acc[i][j]);
        }
    }

    float bvals[4];
#pragma unroll
    for (int j = 0; j < 4; j++) bvals[j] = b2[(size_t)e * DIM + n0 + tx*4 + j];
#pragma unroll
    for (int i = 0; i < 8; i++) {
        int row = m0 + ty*8 + i;
        if (row < cnt) {
            int p = off + row;
            float gt = g_pair_gate[p];
            float4 v;
            v.x = gt * (acc[i][0] + bvals[0]);
            v.y = gt * (acc[i][1] + bvals[1]);
            v.z = gt * (acc[i][2] + bvals[2]);
            v.w = gt * (acc[i][3] + bvals[3]);
            *(float4*)(g_slot + (size_t)p * DIM + n0 + tx*4) = v;
        }
    }
}

// ---------------- combine: fused[t,:] (+)= sum_s slot[pairpos[t,s],:] -------
__global__ __launch_bounds__(256) void combine_kernel(float* __restrict__ out, int accumulate)
{
    int idx = blockIdx.x * 256 + threadIdx.x;   // over N_TOK * (DIM/4)
    if (idx >= N_TOK * (DIM/4)) return;
    int t = idx >> 7;            // DIM/4 = 128 float4 per token
    int d = (idx & 127) << 2;
    float4 acc;
    if (accumulate) acc = *(float4*)(out + (size_t)t * DIM + d);
    else            acc = make_float4(0.f,0.f,0.f,0.f);
#pragma unroll
    for (int s = 0; s < TOPK; s++) {
        int p = g_pairpos[t*TOPK + s];
        float4 v = *(const float4*)(g_slot + (size_t)p * DIM + d);
        acc.x += v.x; acc.y += v.y; acc.z += v.z; acc.w += v.w;
    }
    *(float4*)(out + (size_t)t * DIM + d) = acc;
}

// ---------------- launch --------------------------------------------------
extern "C" void kernel_launch(void* const* d_in, const int* in_sizes, int n_in,
                              void* d_out, int out_size)
{
    const float* view[2]  = {(const float*)d_in[0], (const float*)d_in[1]};
    const float* proj_w   = (const float*)d_in[2];
    const float* proj_b   = (const float*)d_in[3];
    const float* router_w = (const float*)d_in[4];
    const float* keys     = (const float*)d_in[5];
    const float* w1       = (const float*)d_in[6];
    const float* b1       = (const float*)d_in[7];
    const float* w2       = (const float*)d_in[8];
    const float* b2       = (const float*)d_in[9];
    float* out = (float*)d_out;

    float *hP = nullptr, *rP = nullptr;
    cudaGetSymbolAddress((void**)&hP, g_h);
    cudaGetSymbolAddress((void**)&rP, g_r);

    dim3 gproj(DIM/64, N_TOK/128);            // (8, 32)
    dim3 gffn1(HID/64, N_TOK/128, N_EXP);     // (32, 32, 16)
    dim3 gffn2(DIM/64, N_TOK/128, N_EXP);     // (8, 32, 16)

    for (int v = 0; v < 2; v++) {
        // h = x @ proj_w[v] + proj_b[v]
        sgemm_kernel<true><<<gproj, 256>>>(view[v], proj_w + (size_t)v*DIM*DIM,
                                           proj_b + (size_t)v*DIM, hP,
                                           N_TOK, DIM, DIM);
        // r = h @ router_w[v]
        sgemm_kernel<false><<<gproj, 256>>>(hP, router_w + (size_t)v*DIM*DIM,
                                            nullptr, rP, N_TOK, DIM, DIM);
        zero_counts_kernel<<<1, 32>>>();
        gate_kernel<<<N_TOK, 128>>>(keys);
        scan_kernel<<<1, 1>>>();
        scatter_kernel<<<N_TOK/128, 128>>>();
        ffn1_kernel<<<gffn1, 256>>>(w1, b1);
        ffn2_kernel<<<gffn2, 256>>>(w2, b2);
        combine_kernel<<<(N_TOK*(DIM/4) + 255)/256, 256>>>(out, v);
    }
}

// round 2
// speedup vs baseline: 1.0020x; 1.0020x over previous
#include <cuda_runtime.h>
#include <math.h>

// Problem dims (fixed)
#define N_TOK  4096          // B*T
#define DIM    512           // D
#define N_EXP  16            // E
#define TOPK   4             // K
#define HID    2048          // H
#define N_PAIR (N_TOK*TOPK)  // 16384

// ---------------- scratch (device globals; no runtime alloc) ----------------
__device__ float g_h  [N_TOK * DIM];                 // projected tokens (per view)
__device__ float g_r  [N_TOK * DIM];                 // routed tokens
__device__ float g_hid [(size_t)N_PAIR * HID];       // expert hidden (128 MB)
__device__ float g_slot[(size_t)N_PAIR * DIM];       // gated expert output per pair
__device__ int   g_pair_token[N_PAIR];
__device__ float g_pair_gate [N_PAIR];
__device__ int   g_pairpos   [N_TOK * TOPK];         // (token,slot) -> pair position
__device__ int   g_tok_eidx  [N_TOK * TOPK];
__device__ float g_tok_gate  [N_TOK * TOPK];
__device__ int   g_counts [N_EXP];
__device__ int   g_offsets[N_EXP + 1];
__device__ int   g_cursor [N_EXP];

__device__ __forceinline__ float gelu_exact(float x) {
    return 0.5f * x * (1.0f + erff(x * 0.70710678118654752440f));
}

// ---------------- generic SGEMM: C[M,N] = A[M,K] @ B[K,N] (+bias) -----------
// BM=128, BN=64, BK=16, 256 threads, 8x4 per-thread microtile.
template<bool HAS_BIAS>
__global__ __launch_bounds__(256) void sgemm_kernel(
    const float* __restrict__ A, const float* __restrict__ B,
    const float* __restrict__ bias, float* __restrict__ C,
    int M, int N, int K)
{
    __shared__ float As[16][128];
    __shared__ float Bs[16][64];
    const int tid = threadIdx.x;
    const int ty = tid >> 4, tx = tid & 15;
    const int m0 = blockIdx.y * 128;
    const int n0 = blockIdx.x * 64;

    const int la_m = tid >> 1;            // 0..127
    const int la_k = (tid & 1) << 3;      // 0 or 8
    const int lb_k = tid >> 4;            // 0..15
    const int lb_n = (tid & 15) << 2;     // 0..60

    const bool a_valid = (m0 + la_m) < M;
    const float* Arow = A + (size_t)(m0 + la_m) * K + la_k;
    const float* Bptr = B + (size_t)lb_k * N + n0 + lb_n;

    float acc[8][4];
#pragma unroll
    for (int i = 0; i < 8; i++)
#pragma unroll
        for (int j = 0; j < 4; j++) acc[i][j] = 0.f;

    for (int k0 = 0; k0 < K; k0 += 16) {
        float4 a0 = make_float4(0.f,0.f,0.f,0.f), a1 = a0;
        if (a_valid) {
            a0 = *(const float4*)(Arow + k0);
            a1 = *(const float4*)(Arow + k0 + 4);
        }
        float4 b = *(const float4*)(Bptr + (size_t)k0 * N);
        __syncthreads();
        As[la_k+0][la_m] = a0.x; As[la_k+1][la_m] = a0.y;
        As[la_k+2][la_m] = a0.z; As[la_k+3][la_m] = a0.w;
        As[la_k+4][la_m] = a1.x; As[la_k+5][la_m] = a1.y;
        As[la_k+6][la_m] = a1.z; As[la_k+7][la_m] = a1.w;
        *(float4*)&Bs[lb_k][lb_n] = b;
        __syncthreads();
#pragma unroll
        for (int kk = 0; kk < 16; kk++) {
            float4 av0 = *(const float4*)&As[kk][ty*8];
            float4 av1 = *(const float4*)&As[kk][ty*8+4];
            float4 bv  = *(const float4*)&Bs[kk][tx*4];
            float a[8] = {av0.x,av0.y,av0.z,av0.w,av1.x,av1.y,av1.z,av1.w};
            float bb[4] = {bv.x,bv.y,bv.z,bv.w};
#pragma unroll
            for (int i = 0; i < 8; i++)
#pragma unroll
                for (int j = 0; j < 4; j++)
                    acc[i][j] = fmaf(a[i], bb[j], acc[i][j]);
        }
    }

    float bvals[4] = {0.f,0.f,0.f,0.f};
    if (HAS_BIAS) {
#pragma unroll
        for (int j = 0; j < 4; j++) bvals[j] = bias[n0 + tx*4 + j];
    }
#pragma unroll
    for (int i = 0; i < 8; i++) {
        int row = m0 + ty*8 + i;
        if (row < M) {
            float4 v = make_float4(acc[i][0]+bvals[0], acc[i][1]+bvals[1],
                                   acc[i][2]+bvals[2], acc[i][3]+bvals[3]);
            *(float4*)(C + (size_t)row * N + n0 + tx*4) = v;
        }
    }
}

// ---------------- gate: -cdist to expert keys, top-4 softmax ----------------
__global__ __launch_bounds__(128) void gate_kernel(const float* __restrict__ keys)
{
    const int t = blockIdx.x;
    __shared__ float rs[DIM];
    __shared__ float part[N_EXP][8];
    __shared__ float logit[N_EXP];
    const int tid = threadIdx.x;

    for (int i = tid; i < DIM; i += 128) rs[i] = g_r[(size_t)t * DIM + i];
    __syncthreads();

    const int e = tid >> 3;   // 0..15
    const int l = tid & 7;    // 0..7
    const float* kp = keys + (size_t)e * DIM;
    float s = 0.f;
    for (int i = l; i < DIM; i += 8) {
        float d = rs[i] - kp[i];
        s = fmaf(d, d, s);
    }
    part[e][l] = s;
    __syncthreads();
    if (l == 0) {
        float d2 = 0.f;
#pragma unroll
        for (int j = 0; j < 8; j++) d2 += part[e][j];
        logit[e] = -sqrtf(fmaxf(d2, 0.f));
    }
    __syncthreads();
    if (tid == 0) {
        float lv[N_EXP];
#pragma unroll
        for (int i = 0; i < N_EXP; i++) lv[i] = logit[i];
        int   idx[TOPK];
        float val[TOPK];
        bool used[N_EXP];
#pragma unroll
        for (int i = 0; i < N_EXP; i++) used[i] = false;
        for (int s2 = 0; s2 < TOPK; s2++) {
            int bi = -1; float bv = -1e30f;
            for (int i = 0; i < N_EXP; i++)
                if (!used[i] && lv[i] > bv) { bv = lv[i]; bi = i; }
            used[bi] = true; idx[s2] = bi; val[s2] = bv;
        }
        float mx = val[0];   // descending order, val[0] is max
        float ex[TOPK], se = 0.f;
        for (int s2 = 0; s2 < TOPK; s2++) { ex[s2] = expf(val[s2] - mx); se += ex[s2]; }
        float inv = 1.0f / se;
        for (int s2 = 0; s2 < TOPK; s2++) {
            g_tok_eidx[t*TOPK + s2] = idx[s2];
            g_tok_gate[t*TOPK + s2] = ex[s2] * inv;
            atomicAdd(&g_counts[idx[s2]], 1);
        }
    }
}

__global__ void zero_counts_kernel() {
    if (threadIdx.x < N_EXP) g_counts[threadIdx.x] = 0;
}

__global__ void scan_kernel() {
    if (threadIdx.x == 0) {
        int o = 0;
        for (int e = 0; e < N_EXP; e++) {
            g_offsets[e] = o;
            g_cursor[e]  = o;
            o += g_counts[e];
        }
        g_offsets[N_EXP] = o;
    }
}

__global__ __launch_bounds__(128) void scatter_kernel() {
    int t = blockIdx.x * 128 + threadIdx.x;
    if (t >= N_TOK) return;
    for (int s = 0; s < TOPK; s++) {
        int e = g_tok_eidx[t*TOPK + s];
        int p = atomicAdd(&g_cursor[e], 1);
        g_pair_token[p] = t;
        g_pair_gate[p]  = g_tok_gate[t*TOPK + s];
        g_pairpos[t*TOPK + s] = p;
    }
}

// ---------------- FFN1: hid[p,:] = gelu(h[tok(p)] @ w1[e] + b1[e]) ----------
__global__ __launch_bounds__(256) void ffn1_kernel(
    const float* __restrict__ w1, const float* __restrict__ b1)
{
    const int e   = blockIdx.z;
    const int off = g_offsets[e];
    const int cnt = g_offsets[e+1] - off;
    const int m0  = blockIdx.y * 128;
    if (m0 >= cnt) return;
    const int n0  = blockIdx.x * 64;

    __shared__ float As[16][128];
    __shared__ float Bs[16][64];
    const int tid = threadIdx.x;
    const int ty = tid >> 4, tx = tid & 15;
    const int la_m = tid >> 1;
    const int la_k = (tid & 1) << 3;
    const int lb_k = tid >> 4;
    const int lb_n = (tid & 15) << 2;

    const bool a_valid = (m0 + la_m) < cnt;
    const int token = a_valid ? g_pair_token[off + m0 + la_m] : 0;
    const float* Arow = g_h + (size_t)token * DIM + la_k;
    const float* Bptr = w1 + (size_t)e * DIM * HID + (size_t)lb_k * HID + n0 + lb_n;

    float acc[8][4];
#pragma unroll
    for (int i = 0; i < 8; i++)
#pragma unroll
        for (int j = 0; j < 4; j++) acc[i][j] = 0.f;

    for (int k0 = 0; k0 < DIM; k0 += 16) {
        float4 a0 = make_float4(0.f,0.f,0.f,0.f), a1 = a0;
        if (a_valid) {
            a0 = *(const float4*)(Arow + k0);
            a1 = *(const float4*)(Arow + k0 + 4);
        }
        float4 b = *(const float4*)(Bptr + (size_t)k0 * HID);
        __syncthreads();
        As[la_k+0][la_m] = a0.x; As[la_k+1][la_m] = a0.y;
        As[la_k+2][la_m] = a0.z; As[la_k+3][la_m] = a0.w;
        As[la_k+4][la_m] = a1.x; As[la_k+5][la_m] = a1.y;
        As[la_k+6][la_m] = a1.z; As[la_k+7][la_m] = a1.w;
        *(float4*)&Bs[lb_k][lb_n] = b;
        __syncthreads();
#pragma unroll
        for (int kk = 0; kk < 16; kk++) {
            float4 av0 = *(const float4*)&As[kk][ty*8];
            float4 av1 = *(const float4*)&As[kk][ty*8+4];
            float4 bv  = *(const float4*)&Bs[kk][tx*4];
            float a[8] = {av0.x,av0.y,av0.z,av0.w,av1.x,av1.y,av1.z,av1.w};
            float bb[4] = {bv.x,bv.y,bv.z,bv.w};
#pragma unroll
            for (int i = 0; i < 8; i++)
#pragma unroll
                for (int j = 0; j < 4; j++)
                    acc[i][j] = fmaf(a[i], bb[j], acc[i][j]);
        }
    }

    float bvals[4];
#pragma unroll
    for (int j = 0; j < 4; j++) bvals[j] = b1[(size_t)e * HID + n0 + tx*4 + j];
#pragma unroll
    for (int i = 0; i < 8; i++) {
        int row = m0 + ty*8 + i;
        if (row < cnt) {
            int p = off + row;
            float4 v;
            v.x = gelu_exact(acc[i][0] + bvals[0]);
            v.y = gelu_exact(acc[i][1] + bvals[1]);
            v.z = gelu_exact(acc[i][2] + bvals[2]);
            v.w = gelu_exact(acc[i][3] + bvals[3]);
            *(float4*)(g_hid + (size_t)p * HID + n0 + tx*4) = v;
        }
    }
}

// ---------------- FFN2: slot[p,:] = gate[p] * (hid[p] @ w2[e] + b2[e]) ------
__global__ __launch_bounds__(256) void ffn2_kernel(
    const float* __restrict__ w2, const float* __restrict__ b2)
{
    const int e   = blockIdx.z;
    const int off = g_offsets[e];
    const int cnt = g_offsets[e+1] - off;
    const int m0  = blockIdx.y * 128;
    if (m0 >= cnt) return;
    const int n0  = blockIdx.x * 64;

    __shared__ float As[16][128];
    __shared__ float Bs[16][64];
    const int tid = threadIdx.x;
    const int ty = tid >> 4, tx = tid & 15;
    const int la_m = tid >> 1;
    const int la_k = (tid & 1) << 3;
    const int lb_k = tid >> 4;
    const int lb_n = (tid & 15) << 2;

    const bool a_valid = (m0 + la_m) < cnt;
    const float* Arow = g_hid + (size_t)(off + (a_valid ? (m0 + la_m) : 0)) * HID + la_k;
    const float* Bptr = w2 + (size_t)e * HID * DIM + (size_t)lb_k * DIM + n0 + lb_n;

    float acc[8][4];
#pragma unroll
    for (int i = 0; i < 8; i++)
#pragma unroll
        for (int j = 0; j < 4; j++) acc[i][j] = 0.f;

    for (int k0 = 0; k0 < HID; k0 += 16) {
        float4 a0 = make_float4(0.f,0.f,0.f,0.f), a1 = a0;
        if (a_valid) {
            a0 = *(const float4*)(Arow + k0);
            a1 = *(const float4*)(Arow + k0 + 4);
        }
        float4 b = *(const float4*)(Bptr + (size_t)k0 * DIM);
        __syncthreads();
        As[la_k+0][la_m] = a0.x; As[la_k+1][la_m] = a0.y;
        As[la_k+2][la_m] = a0.z; As[la_k+3][la_m] = a0.w;
        As[la_k+4][la_m] = a1.x; As[la_k+5][la_m] = a1.y;
        As[la_k+6][la_m] = a1.z; As[la_k+7][la_m] = a1.w;
        *(float4*)&Bs[lb_k][lb_n] = b;
        __syncthreads();
#pragma unroll
        for (int kk = 0; kk < 16; kk++) {
            float4 av0 = *(const float4*)&As[kk][ty*8];
            float4 av1 = *(const float4*)&As[kk][ty*8+4];
            float4 bv  = *(const float4*)&Bs[kk][tx*4];
            float a[8] = {av0.x,av0.y,av0.z,av0.w,av1.x,av1.y,av1.z,av1.w};
            float bb[4] = {bv.x,bv.y,bv.z,bv.w};
#pragma unroll
            for (int i = 0; i < 8; i++)
#pragma unroll
                for (int j = 0; j < 4; j++)
                    acc[i][j] = fmaf(a[i], bb[j], acc[i][j]);
        }
    }

    float bvals[4];
#pragma unroll
    for (int j = 0; j < 4; j++) bvals[j] = b2[(size_t)e * DIM + n0 + tx*4 + j];
#pragma unroll
    for (int i = 0; i < 8; i++) {
        int row = m0 + ty*8 + i;
        if (row < cnt) {
            int p = off + row;
            float gt = g_pair_gate[p];
            float4 v;
            v.x = gt * (acc[i][0] + bvals[0]);
            v.y = gt * (acc[i][1] + bvals[1]);
            v.z = gt * (acc[i][2] + bvals[2]);
            v.w = gt * (acc[i][3] + bvals[3]);
            *(float4*)(g_slot + (size_t)p * DIM + n0 + tx*4) = v;
        }
    }
}

// ---------------- combine: fused[t,:] (+)= sum_s slot[pairpos[t,s],:] -------
__global__ __launch_bounds__(256) void combine_kernel(float* __restrict__ out, int accumulate)
{
    int idx = blockIdx.x * 256 + threadIdx.x;   // over N_TOK * (DIM/4)
    if (idx >= N_TOK * (DIM/4)) return;
    int t = idx >> 7;            // DIM/4 = 128 float4 per token
    int d = (idx & 127) << 2;
    float4 acc;
    if (accumulate) acc = *(float4*)(out + (size_t)t * DIM + d);
    else            acc = make_float4(0.f,0.f,0.f,0.f);
#pragma unroll
    for (int s = 0; s < TOPK; s++) {
        int p = g_pairpos[t*TOPK + s];
        float4 v = *(const float4*)(g_slot + (size_t)p * DIM + d);
        acc.x += v.x; acc.y += v.y; acc.z += v.z; acc.w += v.w;
    }
    *(float4*)(out + (size_t)t * DIM + d) = acc;
}

// ---------------- launch --------------------------------------------------
extern "C" void kernel_launch(void* const* d_in, const int* in_sizes, int n_in,
                              void* d_out, int out_size)
{
    const float* view[2]  = {(const float*)d_in[0], (const float*)d_in[1]};
    const float* proj_w   = (const float*)d_in[2];
    const float* proj_b   = (const float*)d_in[3];
    const float* router_w = (const float*)d_in[4];
    const float* keys     = (const float*)d_in[5];
    const float* w1       = (const float*)d_in[6];
    const float* b1       = (const float*)d_in[7];
    const float* w2       = (const float*)d_in[8];
    const float* b2       = (const float*)d_in[9];
    float* out = (float*)d_out;

    float *hP = nullptr, *rP = nullptr;
    cudaGetSymbolAddress((void**)&hP, g_h);
    cudaGetSymbolAddress((void**)&rP, g_r);

    dim3 gproj(DIM/64, N_TOK/128);            // (8, 32)
    dim3 gffn1(HID/64, N_TOK/128, N_EXP);     // (32, 32, 16)
    dim3 gffn2(DIM/64, N_TOK/128, N_EXP);     // (8, 32, 16)

    for (int v = 0; v < 2; v++) {
        // h = x @ proj_w[v] + proj_b[v]
        sgemm_kernel<true><<<gproj, 256>>>(view[v], proj_w + (size_t)v*DIM*DIM,
                                           proj_b + (size_t)v*DIM, hP,
                                           N_TOK, DIM, DIM);
        // r = h @ router_w[v]
        sgemm_kernel<false><<<gproj, 256>>>(hP, router_w + (size_t)v*DIM*DIM,
                                            nullptr, rP, N_TOK, DIM, DIM);
        zero_counts_kernel<<<1, 32>>>();
        gate_kernel<<<N_TOK, 128>>>(keys);
        scan_kernel<<<1, 1>>>();
        scatter_kernel<<<N_TOK/128, 128>>>();
        ffn1_kernel<<<gffn1, 256>>>(w1, b1);
        ffn2_kernel<<<gffn2, 256>>>(w2, b2);
        combine_kernel<<<(N_TOK*(DIM/4) + 255)/256, 256>>>(out, v);
    }
}